// round 11
// baseline (speedup 1.0000x reference)
#include <cuda_runtime.h>
#include <cstdint>

#define SEQ   1000
#define IDIM  900
#define HDIM  4096
#define WOLD  (HDIM + IDIM + 1)   // 4997, W_out row stride
#define NBLK  148
#define TPB   512
#define CACHE_ROWS 13
// w cache + reduction buffer (4*28 floats, padded)
#define LOOP_SMEM ((CACHE_ROWS * HDIM + 128) * sizeof(float))

typedef unsigned long long ull;

// ---------------- scratch (static device globals; no allocation) ----------------
__device__ float g_U[SEQ * HDIM];   // W_ih @ inp[t]   (t-major)
__device__ float g_P[SEQ * IDIM];   // bias + input part of readout
__device__ int   g_bar;             // monotonic arrival counter

__device__ __forceinline__ int ld_acq(const int* p) {
    int v;
    asm volatile("ld.acquire.gpu.b32 %0, [%1];" : "=r"(v) : "l"(p) : "memory");
    return v;
}
__device__ __forceinline__ void arrive_release(int* p) {
    asm volatile("red.release.gpu.global.add.s32 [%0], 1;" :: "l"(p) : "memory");
}
// packed f32x2 FMA (Blackwell FFMA2 — only reachable via PTX)
__device__ __forceinline__ ull fma2(ull a, ull b, ull c) {
    ull d;
    asm("fma.rn.f32x2 %0, %1, %2, %3;" : "=l"(d) : "l"(a), "l"(b), "l"(c));
    return d;
}
__device__ __forceinline__ float accsum(ull a) {
    return __uint_as_float((unsigned)a) + __uint_as_float((unsigned)(a >> 32));
}
__device__ __forceinline__ ull dupf(float a) {
    ull d;
    unsigned ai = __float_as_uint(a);
    asm("mov.b64 %0, {%1, %1};" : "=l"(d) : "r"(ai));
    return d;
}

__global__ void reset_kernel() {
    if (threadIdx.x == 0) g_bar = 0;
}

// ---------------- persistent recurrence kernel ----------------
// s_{t} = tanh(U[t] + W_hh @ s_{t-1});  states[t] = s_t
// 148 blocks (1/SM), 512 threads, split-K-4: warp w = (q, kq) with q=w>>2,
// kq=w&3 computes rows {q+4i, i=0..6} over k-quarter kq (f32x2 FMAs).
// s is read DIRECTLY from states[t-1] in L2 (no SMEM staging): the 4 warps
// sharing a k-quarter hit L1 after the first. Row-quarters i=4,5 (rows q+16,
// q+20) are persistently register-cached; rows <13 SMEM-resident; the rest
// stream from L2. Partials combine via SMEM in warp 0; warp 15 polls the
// single-counter grid barrier.
__global__ __launch_bounds__(TPB, 1) void esn_loop_kernel(
    const float* __restrict__ W_hh,
    const float* __restrict__ s0,
    float* __restrict__ states)
{
    extern __shared__ float sh[];
    float* w_sh   = sh;                          // CACHE_ROWS * HDIM
    float* red_sh = sh + CACHE_ROWS * HDIM;      // 4*28 floats

    const int bid  = blockIdx.x;
    const int tid  = threadIdx.x;
    const int warp = tid >> 5;
    const int lane = tid & 31;

    // 4096 = 148*27 + 100 -> blocks 0..99 get 28 rows, 100..147 get 27
    const int base  = bid * 27 + (bid < 100 ? bid : 100);
    const int nrows = (bid < 100) ? 28 : 27;

    // prologue: cache first CACHE_ROWS rows of this block's slice in SMEM
    {
        const float4* wsrc = (const float4*)(W_hh + (size_t)base * HDIM);
        float4* wdst = (float4*)w_sh;
        for (int i = tid; i < CACHE_ROWS * (HDIM / 4); i += TPB) wdst[i] = wsrc[i];
    }

    const int q  = warp >> 2;         // row-group 0..3
    const int kq = warp & 3;          // k-quarter
    const int kbase = kq * 256;       // in 16B units (256 ulonglong2 per quarter)

    // rows i=0..3 (q,q+4,q+8,q+12): SMEM if <13 else L2; row i=6 (q+24): L2
    const ulonglong2* wp0; const ulonglong2* wp1;
    const ulonglong2* wp2; const ulonglong2* wp3; const ulonglong2* wp6;
    {
        int r0 = q,      r1 = q + 4,  r2 = q + 8;
        int r3 = q + 12; int r6 = q + 24;
        int c3 = r3 < nrows ? r3 : nrows - 1;
        int c6 = r6 < nrows ? r6 : nrows - 1;   // row 27 invalid when nrows=27
        wp0 = (const ulonglong2*)(w_sh + r0 * HDIM);
        wp1 = (const ulonglong2*)(w_sh + r1 * HDIM);
        wp2 = (const ulonglong2*)(w_sh + r2 * HDIM);
        wp3 = (r3 < CACHE_ROWS) ? (const ulonglong2*)(w_sh + r3 * HDIM)
                                : (const ulonglong2*)(W_hh + (size_t)(base + c3) * HDIM);
        wp6 = (const ulonglong2*)(W_hh + (size_t)(base + c6) * HDIM);
    }
    // persistent register cache: k-quarter of rows q+16 (i=4) and q+20 (i=5)
    ulonglong2 wc4[8], wc5[8];
    {
        const ulonglong2* p4 = (const ulonglong2*)(W_hh + (size_t)(base + q + 16) * HDIM);
        const ulonglong2* p5 = (const ulonglong2*)(W_hh + (size_t)(base + q + 20) * HDIM);
        #pragma unroll
        for (int j = 0; j < 8; ++j) {
            wc4[j] = p4[kbase + lane + j * 32];
            wc5[j] = p5[kbase + lane + j * 32];
        }
    }

    const float* s_src = s0;
    __syncthreads();   // w_sh ready

    for (int t = 0; t < SEQ; ++t) {
        // early, independent U load for the combine phase (hidden under compute)
        float u = 0.f;
        if (warp == 0 && lane < 28) {
            int rc = lane < nrows ? lane : nrows - 1;
            u = g_U[(size_t)t * HDIM + base + rc];
        }

        {
            // s read directly from L2/L1 (no staging)
            const ulonglong2* sq = (const ulonglong2*)s_src;
            ull a0 = 0, a1 = 0, a2 = 0, a3 = 0, a4 = 0, a5 = 0, a6 = 0;

            #pragma unroll
            for (int j = 0; j < 8; ++j) {
                const int idx = kbase + lane + j * 32;
                ulonglong2 s2 = sq[idx];
                ulonglong2 w0 = wp0[idx];
                ulonglong2 w1 = wp1[idx];
                ulonglong2 w2 = wp2[idx];
                ulonglong2 w3 = wp3[idx];
                ulonglong2 w6 = wp6[idx];
                a0 = fma2(w0.x, s2.x, a0); a0 = fma2(w0.y, s2.y, a0);
                a1 = fma2(w1.x, s2.x, a1); a1 = fma2(w1.y, s2.y, a1);
                a2 = fma2(w2.x, s2.x, a2); a2 = fma2(w2.y, s2.y, a2);
                a3 = fma2(w3.x, s2.x, a3); a3 = fma2(w3.y, s2.y, a3);
                a4 = fma2(wc4[j].x, s2.x, a4); a4 = fma2(wc4[j].y, s2.y, a4);
                a5 = fma2(wc5[j].x, s2.x, a5); a5 = fma2(wc5[j].y, s2.y, a5);
                a6 = fma2(w6.x, s2.x, a6); a6 = fma2(w6.y, s2.y, a6);
            }

            float r0 = accsum(a0), r1 = accsum(a1), r2 = accsum(a2), r3 = accsum(a3);
            float r4 = accsum(a4), r5 = accsum(a5), r6 = accsum(a6);
            #pragma unroll
            for (int off = 16; off; off >>= 1) {
                r0 += __shfl_xor_sync(0xffffffffu, r0, off);
                r1 += __shfl_xor_sync(0xffffffffu, r1, off);
                r2 += __shfl_xor_sync(0xffffffffu, r2, off);
                r3 += __shfl_xor_sync(0xffffffffu, r3, off);
                r4 += __shfl_xor_sync(0xffffffffu, r4, off);
                r5 += __shfl_xor_sync(0xffffffffu, r5, off);
                r6 += __shfl_xor_sync(0xffffffffu, r6, off);
            }
            if (lane == 0) {
                float* rp = red_sh + kq * 28 + q;
                rp[0]  = r0; rp[4]  = r1; rp[8]  = r2; rp[12] = r3;
                rp[16] = r4; rp[20] = r5; rp[24] = r6;
            }
        }
        __syncthreads();   // partials visible

        if (warp == 0 && lane < 28) {
            float v = red_sh[lane] + red_sh[28 + lane]
                    + red_sh[56 + lane] + red_sh[84 + lane];
            if (lane < nrows)
                states[(size_t)t * HDIM + base + lane] = tanhf(v + u);
        }
        __syncthreads();   // states STGs of this step issued

        if (t < SEQ - 1) {
            if (tid == 0) arrive_release(&g_bar);   // release: orders the STGs
            if (warp == 15) {                       // poller
                const int target = (t + 1) * NBLK;
                while (ld_acq(&g_bar) < target) { }
            }
            __syncthreads();   // barrier passed; also protects red_sh reuse
        }

        s_src = states + (size_t)t * HDIM;
    }
}

// ---------------- fp32 GEMM: C[n][m] = (bias[m]) + (Cadd[n][m]) + sum_k A[m][k]*B[n][k]
// A: M x K row stride lda (float4 when aligned, else scalar)
// B: N x K row stride ldb (float4 when aligned)
// 256 threads, BMxBN tile, BK=8, (BM/16)x(BN/16) microtile, packed f32x2 FMAs.
template<int BM, int BN>
__global__ __launch_bounds__(256, 2) void gemm_nt(
    const float* __restrict__ A, int lda,
    const float* __restrict__ B, int ldb,
    float* __restrict__ C, int ldc,
    const float* __restrict__ Cadd,
    const float* __restrict__ bias, int bias_stride,
    int M, int N, int K)
{
    constexpr int BK = 8;
    constexpr int TM = BM / 16;
    constexpr int TN = BN / 16;
    constexpr int TN2 = TN / 2;
    __shared__ float As[BK][BM + 4];
    __shared__ float Bs[BK][BN + 4];

    const int tid = threadIdx.x;
    const int tx = tid & 15;
    const int ty = tid >> 4;
    const int m0 = blockIdx.x * BM;
    const int n0 = blockIdx.y * BN;

    const bool a_vec = ((reinterpret_cast<uintptr_t>(A) & 15) == 0) && ((lda & 3) == 0);
    const bool b_vec = ((reinterpret_cast<uintptr_t>(B) & 15) == 0) && ((ldb & 3) == 0);

    ull acc2[TM][TN2];
    #pragma unroll
    for (int i = 0; i < TM; ++i)
        #pragma unroll
        for (int j = 0; j < TN2; ++j) acc2[i][j] = 0ull;

    for (int kt = 0; kt < K; kt += BK) {
        // ---- load A tile (BM x 8) transposed into As ----
        #pragma unroll
        for (int i = tid; i < BM * 2; i += 256) {
            int m = i >> 1;
            int kq = (i & 1) * 4;
            int gm = m0 + m;
            float v0 = 0.f, v1 = 0.f, v2 = 0.f, v3 = 0.f;
            if (gm < M) {
                const float* p = A + (size_t)gm * lda + (kt + kq);
                int rem = K - (kt + kq);
                if (a_vec && rem >= 4) {
                    float4 v = *(const float4*)p;
                    v0 = v.x; v1 = v.y; v2 = v.z; v3 = v.w;
                } else {
                    if (rem > 0) v0 = p[0];
                    if (rem > 1) v1 = p[1];
                    if (rem > 2) v2 = p[2];
                    if (rem > 3) v3 = p[3];
                }
            }
            As[kq + 0][m] = v0; As[kq + 1][m] = v1;
            As[kq + 2][m] = v2; As[kq + 3][m] = v3;
        }
        // ---- load B tile (BN x 8) transposed into Bs ----
        #pragma unroll
        for (int i = tid; i < BN * 2; i += 256) {
            int n = i >> 1;
            int kq = (i & 1) * 4;
            int gn = n0 + n;
            int gk = kt + kq;
            float v0 = 0.f, v1 = 0.f, v2 = 0.f, v3 = 0.f;
            if (gn < N) {
                const float* p = B + (size_t)gn * ldb + gk;
                int rem = K - gk;
                if (b_vec && rem >= 4) {
                    float4 v = *(const float4*)p;
                    v0 = v.x; v1 = v.y; v2 = v.z; v3 = v.w;
                } else {
                    if (rem > 0) v0 = p[0];
                    if (rem > 1) v1 = p[1];
                    if (rem > 2) v2 = p[2];
                    if (rem > 3) v3 = p[3];
                }
            }
            Bs[kq + 0][n] = v0; Bs[kq + 1][n] = v1;
            Bs[kq + 2][n] = v2; Bs[kq + 3][n] = v3;
        }
        __syncthreads();

        #pragma unroll
        for (int kk = 0; kk < BK; ++kk) {
            ull ap[TM], b2[TN2];
            #pragma unroll
            for (int i = 0; i < TM; ++i) ap[i] = dupf(As[kk][ty * TM + i]);
            #pragma unroll
            for (int j = 0; j < TN2; ++j)
                b2[j] = *(const ull*)&Bs[kk][tx * TN + 2 * j];   // 8B-aligned
            #pragma unroll
            for (int i = 0; i < TM; ++i)
                #pragma unroll
                for (int j = 0; j < TN2; ++j)
                    acc2[i][j] = fma2(ap[i], b2[j], acc2[i][j]);
        }
        __syncthreads();
    }

    // ---- epilogue ----
    #pragma unroll
    for (int i = 0; i < TM; ++i) {
        int gm = m0 + ty * TM + i;
        if (gm >= M) continue;
        float bv = bias ? bias[(size_t)gm * bias_stride] : 0.f;
        #pragma unroll
        for (int j = 0; j < TN2; ++j) {
            float vlo = __uint_as_float((unsigned)acc2[i][j]);
            float vhi = __uint_as_float((unsigned)(acc2[i][j] >> 32));
            int gn0 = n0 + tx * TN + 2 * j;
            if (gn0 < N) {
                float v = vlo + bv;
                if (Cadd) v += Cadd[(size_t)gn0 * ldc + gm];
                C[(size_t)gn0 * ldc + gm] = v;
            }
            if (gn0 + 1 < N) {
                float v = vhi + bv;
                if (Cadd) v += Cadd[(size_t)(gn0 + 1) * ldc + gm];
                C[(size_t)(gn0 + 1) * ldc + gm] = v;
            }
        }
    }
}

// ---------------- launch ----------------
extern "C" void kernel_launch(void* const* d_in, const int* in_sizes, int n_in,
                              void* d_out, int out_size)
{
    const float* inputs = (const float*)d_in[0];  // (1000,1,900)
    const float* state0 = (const float*)d_in[1];  // (1,4096)
    const float* W_ih   = (const float*)d_in[2];  // (4096,900)
    const float* W_hh   = (const float*)d_in[3];  // (4096,4096)
    const float* W_out  = (const float*)d_in[4];  // (900,4997)

    float* out    = (float*)d_out;                // outputs: SEQ*IDIM
    float* states = out + (size_t)SEQ * IDIM;     // states : SEQ*HDIM

    float *U = nullptr, *P = nullptr;
    cudaGetSymbolAddress((void**)&U, g_U);
    cudaGetSymbolAddress((void**)&P, g_P);

    cudaFuncSetAttribute(esn_loop_kernel,
                         cudaFuncAttributeMaxDynamicSharedMemorySize, (int)LOOP_SMEM);

    reset_kernel<<<1, 32>>>();

    // U[t][h] = W_ih[h,:] . inp[t,:]            M=4096 N=1000 K=900
    gemm_nt<128, 64><<<dim3(HDIM / 128, (SEQ + 63) / 64), 256>>>(
        W_ih, IDIM, inputs, IDIM, U, HDIM,
        nullptr, nullptr, 0, HDIM, SEQ, IDIM);

    // P[t][i] = W_out[i][0] + W_out[i,1:901] . inp[t,:]   M=900 N=1000 K=900
    gemm_nt<64, 64><<<dim3((IDIM + 63) / 64, (SEQ + 63) / 64), 256>>>(
        W_out + 1, WOLD, inputs, IDIM, P, IDIM,
        nullptr, W_out, WOLD, IDIM, SEQ, IDIM);

    // sequential recurrence: states[t] = tanh(U[t] + W_hh @ states[t-1])
    esn_loop_kernel<<<NBLK, TPB, LOOP_SMEM>>>(W_hh, state0, states);

    // out[t][i] = P[t][i] + W_out[i,901:] . states[t,:]   M=900 N=1000 K=4096
    gemm_nt<64, 64><<<dim3((IDIM + 63) / 64, (SEQ + 63) / 64), 256>>>(
        W_out + 1 + IDIM, WOLD, states, HDIM, out, IDIM,
        P, nullptr, 0, IDIM, SEQ, HDIM);
}

// round 12
// speedup vs baseline: 1.1109x; 1.1109x over previous
#include <cuda_runtime.h>
#include <cstdint>

#define SEQ   1000
#define IDIM  900
#define HDIM  4096
#define WOLD  (HDIM + IDIM + 1)   // 4997, W_out row stride
#define NBLK  148
#define TPB   512
#define CACHE_ROWS 13
// w cache + s buffer + reduction buffer (4*28 floats, padded)
#define LOOP_SMEM ((CACHE_ROWS * HDIM + HDIM + 128) * sizeof(float))

typedef unsigned long long ull;

// ---------------- scratch (static device globals; no allocation) ----------------
__device__ float g_U[SEQ * HDIM];   // W_ih @ inp[t]   (t-major)
__device__ float g_P[SEQ * IDIM];   // bias + input part of readout
__device__ int   g_bar;             // monotonic arrival counter

__device__ __forceinline__ int ld_acq(const int* p) {
    int v;
    asm volatile("ld.acquire.gpu.b32 %0, [%1];" : "=r"(v) : "l"(p) : "memory");
    return v;
}
__device__ __forceinline__ void arrive_release(int* p) {
    asm volatile("red.release.gpu.global.add.s32 [%0], 1;" :: "l"(p) : "memory");
}
// packed f32x2 FMA (Blackwell FFMA2 — only reachable via PTX)
__device__ __forceinline__ ull fma2(ull a, ull b, ull c) {
    ull d;
    asm("fma.rn.f32x2 %0, %1, %2, %3;" : "=l"(d) : "l"(a), "l"(b), "l"(c));
    return d;
}
__device__ __forceinline__ float accsum(ull a) {
    return __uint_as_float((unsigned)a) + __uint_as_float((unsigned)(a >> 32));
}
__device__ __forceinline__ ull dupf(float a) {
    ull d;
    unsigned ai = __float_as_uint(a);
    asm("mov.b64 %0, {%1, %1};" : "=l"(d) : "r"(ai));
    return d;
}

__global__ void reset_kernel() {
    if (threadIdx.x == 0) g_bar = 0;
}

// ---------------- persistent recurrence kernel ----------------
// s_{t} = tanh(U[t] + W_hh @ s_{t-1});  states[t] = s_t
// 148 blocks (1/SM), 512 threads, split-K-4: warp w = (q, kq) with q=w>>2,
// kq=w&3 computes rows {q+4i, i=0..6} over k-quarter kq (f32x2 FMAs).
// s is staged into SMEM once per step (R10 structure). Row-quarters i=4,5
// (rows q+16, q+20) are persistently register-cached; rows <13 SMEM-resident;
// the rest stream from L2. Warp 0 combines partials + tanh + stores, then
// arrives via __syncwarp + red.release (no extra block sync). Warp 15 polls
// the single-counter grid barrier. 3 __syncthreads per step.
__global__ __launch_bounds__(TPB, 1) void esn_loop_kernel(
    const float* __restrict__ W_hh,
    const float* __restrict__ s0,
    float* __restrict__ states)
{
    extern __shared__ float sh[];
    float* w_sh   = sh;                          // CACHE_ROWS * HDIM
    float* s_sh   = sh + CACHE_ROWS * HDIM;      // HDIM
    float* red_sh = s_sh + HDIM;                 // 4*28 floats

    const int bid  = blockIdx.x;
    const int tid  = threadIdx.x;
    const int warp = tid >> 5;
    const int lane = tid & 31;

    // 4096 = 148*27 + 100 -> blocks 0..99 get 28 rows, 100..147 get 27
    const int base  = bid * 27 + (bid < 100 ? bid : 100);
    const int nrows = (bid < 100) ? 28 : 27;

    // prologue: cache first CACHE_ROWS rows of this block's slice in SMEM
    {
        const float4* wsrc = (const float4*)(W_hh + (size_t)base * HDIM);
        float4* wdst = (float4*)w_sh;
        for (int i = tid; i < CACHE_ROWS * (HDIM / 4); i += TPB) wdst[i] = wsrc[i];
    }

    const int q  = warp >> 2;         // row-group 0..3
    const int kq = warp & 3;          // k-quarter
    const int kbase = kq * 256;       // in 16B units (256 ulonglong2 per quarter)

    // rows i=0..3 (q,q+4,q+8,q+12): SMEM if <13 else L2; row i=6 (q+24): L2
    const ulonglong2* wp0; const ulonglong2* wp1;
    const ulonglong2* wp2; const ulonglong2* wp3; const ulonglong2* wp6;
    {
        int r0 = q,      r1 = q + 4,  r2 = q + 8;
        int r3 = q + 12; int r6 = q + 24;
        int c3 = r3 < nrows ? r3 : nrows - 1;
        int c6 = r6 < nrows ? r6 : nrows - 1;   // row 27 invalid when nrows=27
        wp0 = (const ulonglong2*)(w_sh + r0 * HDIM);
        wp1 = (const ulonglong2*)(w_sh + r1 * HDIM);
        wp2 = (const ulonglong2*)(w_sh + r2 * HDIM);
        wp3 = (r3 < CACHE_ROWS) ? (const ulonglong2*)(w_sh + r3 * HDIM)
                                : (const ulonglong2*)(W_hh + (size_t)(base + c3) * HDIM);
        wp6 = (const ulonglong2*)(W_hh + (size_t)(base + c6) * HDIM);
    }
    // persistent register cache: k-quarter of rows q+16 (i=4) and q+20 (i=5)
    ulonglong2 wc4[8], wc5[8];
    {
        const ulonglong2* p4 = (const ulonglong2*)(W_hh + (size_t)(base + q + 16) * HDIM);
        const ulonglong2* p5 = (const ulonglong2*)(W_hh + (size_t)(base + q + 20) * HDIM);
        #pragma unroll
        for (int j = 0; j < 8; ++j) {
            wc4[j] = p4[kbase + lane + j * 32];
            wc5[j] = p5[kbase + lane + j * 32];
        }
    }

    const float* s_src = s0;

    for (int t = 0; t < SEQ; ++t) {
        // early, independent U load for the combine phase (hidden under compute)
        float u = 0.f;
        if (warp == 0 && lane < 28) {
            int rc = lane < nrows ? lane : nrows - 1;
            u = g_U[(size_t)t * HDIM + base + rc];
        }

        // stage current state vector into SMEM (1024 float4, 512 threads)
        {
            const float4* src = (const float4*)s_src;
            float4* dst = (float4*)s_sh;
            float4 v0 = src[tid];
            float4 v1 = src[tid + TPB];
            dst[tid] = v0;
            dst[tid + TPB] = v1;
        }
        __syncthreads();   // (1) s_sh ready

        {
            const ulonglong2* sq = (const ulonglong2*)s_sh;
            ull a0 = 0, a1 = 0, a2 = 0, a3 = 0, a4 = 0, a5 = 0, a6 = 0;

            #pragma unroll
            for (int j = 0; j < 8; ++j) {
                const int idx = kbase + lane + j * 32;
                ulonglong2 s2 = sq[idx];
                ulonglong2 w0 = wp0[idx];
                ulonglong2 w1 = wp1[idx];
                ulonglong2 w2 = wp2[idx];
                ulonglong2 w3 = wp3[idx];
                ulonglong2 w6 = wp6[idx];
                a0 = fma2(w0.x, s2.x, a0); a0 = fma2(w0.y, s2.y, a0);
                a1 = fma2(w1.x, s2.x, a1); a1 = fma2(w1.y, s2.y, a1);
                a2 = fma2(w2.x, s2.x, a2); a2 = fma2(w2.y, s2.y, a2);
                a3 = fma2(w3.x, s2.x, a3); a3 = fma2(w3.y, s2.y, a3);
                a4 = fma2(wc4[j].x, s2.x, a4); a4 = fma2(wc4[j].y, s2.y, a4);
                a5 = fma2(wc5[j].x, s2.x, a5); a5 = fma2(wc5[j].y, s2.y, a5);
                a6 = fma2(w6.x, s2.x, a6); a6 = fma2(w6.y, s2.y, a6);
            }

            float r0 = accsum(a0), r1 = accsum(a1), r2 = accsum(a2), r3 = accsum(a3);
            float r4 = accsum(a4), r5 = accsum(a5), r6 = accsum(a6);
            #pragma unroll
            for (int off = 16; off; off >>= 1) {
                r0 += __shfl_xor_sync(0xffffffffu, r0, off);
                r1 += __shfl_xor_sync(0xffffffffu, r1, off);
                r2 += __shfl_xor_sync(0xffffffffu, r2, off);
                r3 += __shfl_xor_sync(0xffffffffu, r3, off);
                r4 += __shfl_xor_sync(0xffffffffu, r4, off);
                r5 += __shfl_xor_sync(0xffffffffu, r5, off);
                r6 += __shfl_xor_sync(0xffffffffu, r6, off);
            }
            if (lane == 0) {
                float* rp = red_sh + kq * 28 + q;
                rp[0]  = r0; rp[4]  = r1; rp[8]  = r2; rp[12] = r3;
                rp[16] = r4; rp[20] = r5; rp[24] = r6;
            }
        }
        __syncthreads();   // (2) partials visible

        // warp 0: combine + tanh + store + EARLY arrive (syncwarp orders the
        // lanes' STGs before lane 0's release-add — no block-wide sync needed)
        if (warp == 0) {
            if (lane < 28) {
                float v = red_sh[lane] + red_sh[28 + lane]
                        + red_sh[56 + lane] + red_sh[84 + lane];
                if (lane < nrows)
                    states[(size_t)t * HDIM + base + lane] = tanhf(v + u);
            }
            __syncwarp();
            if (lane == 0 && t < SEQ - 1) arrive_release(&g_bar);
        }

        if (t < SEQ - 1) {
            if (warp == 15) {                       // poller (starts immediately)
                const int target = (t + 1) * NBLK;
                while (ld_acq(&g_bar) < target) { }
            }
            __syncthreads();   // (3) barrier passed; also protects s_sh/red_sh reuse
        }

        s_src = states + (size_t)t * HDIM;
    }
}

// ---------------- fp32 GEMM: C[n][m] = (bias[m]) + (Cadd[n][m]) + sum_k A[m][k]*B[n][k]
// A: M x K row stride lda (float4 when aligned, else scalar)
// B: N x K row stride ldb (float4 when aligned)
// 256 threads, BMxBN tile, BK=8, (BM/16)x(BN/16) microtile, packed f32x2 FMAs.
template<int BM, int BN>
__global__ __launch_bounds__(256, 2) void gemm_nt(
    const float* __restrict__ A, int lda,
    const float* __restrict__ B, int ldb,
    float* __restrict__ C, int ldc,
    const float* __restrict__ Cadd,
    const float* __restrict__ bias, int bias_stride,
    int M, int N, int K)
{
    constexpr int BK = 8;
    constexpr int TM = BM / 16;
    constexpr int TN = BN / 16;
    constexpr int TN2 = TN / 2;
    __shared__ float As[BK][BM + 4];
    __shared__ float Bs[BK][BN + 4];

    const int tid = threadIdx.x;
    const int tx = tid & 15;
    const int ty = tid >> 4;
    const int m0 = blockIdx.x * BM;
    const int n0 = blockIdx.y * BN;

    const bool a_vec = ((reinterpret_cast<uintptr_t>(A) & 15) == 0) && ((lda & 3) == 0);
    const bool b_vec = ((reinterpret_cast<uintptr_t>(B) & 15) == 0) && ((ldb & 3) == 0);

    ull acc2[TM][TN2];
    #pragma unroll
    for (int i = 0; i < TM; ++i)
        #pragma unroll
        for (int j = 0; j < TN2; ++j) acc2[i][j] = 0ull;

    for (int kt = 0; kt < K; kt += BK) {
        // ---- load A tile (BM x 8) transposed into As ----
        #pragma unroll
        for (int i = tid; i < BM * 2; i += 256) {
            int m = i >> 1;
            int kq = (i & 1) * 4;
            int gm = m0 + m;
            float v0 = 0.f, v1 = 0.f, v2 = 0.f, v3 = 0.f;
            if (gm < M) {
                const float* p = A + (size_t)gm * lda + (kt + kq);
                int rem = K - (kt + kq);
                if (a_vec && rem >= 4) {
                    float4 v = *(const float4*)p;
                    v0 = v.x; v1 = v.y; v2 = v.z; v3 = v.w;
                } else {
                    if (rem > 0) v0 = p[0];
                    if (rem > 1) v1 = p[1];
                    if (rem > 2) v2 = p[2];
                    if (rem > 3) v3 = p[3];
                }
            }
            As[kq + 0][m] = v0; As[kq + 1][m] = v1;
            As[kq + 2][m] = v2; As[kq + 3][m] = v3;
        }
        // ---- load B tile (BN x 8) transposed into Bs ----
        #pragma unroll
        for (int i = tid; i < BN * 2; i += 256) {
            int n = i >> 1;
            int kq = (i & 1) * 4;
            int gn = n0 + n;
            int gk = kt + kq;
            float v0 = 0.f, v1 = 0.f, v2 = 0.f, v3 = 0.f;
            if (gn < N) {
                const float* p = B + (size_t)gn * ldb + gk;
                int rem = K - gk;
                if (b_vec && rem >= 4) {
                    float4 v = *(const float4*)p;
                    v0 = v.x; v1 = v.y; v2 = v.z; v3 = v.w;
                } else {
                    if (rem > 0) v0 = p[0];
                    if (rem > 1) v1 = p[1];
                    if (rem > 2) v2 = p[2];
                    if (rem > 3) v3 = p[3];
                }
            }
            Bs[kq + 0][n] = v0; Bs[kq + 1][n] = v1;
            Bs[kq + 2][n] = v2; Bs[kq + 3][n] = v3;
        }
        __syncthreads();

        #pragma unroll
        for (int kk = 0; kk < BK; ++kk) {
            ull ap[TM], b2[TN2];
            #pragma unroll
            for (int i = 0; i < TM; ++i) ap[i] = dupf(As[kk][ty * TM + i]);
            #pragma unroll
            for (int j = 0; j < TN2; ++j)
                b2[j] = *(const ull*)&Bs[kk][tx * TN + 2 * j];   // 8B-aligned
            #pragma unroll
            for (int i = 0; i < TM; ++i)
                #pragma unroll
                for (int j = 0; j < TN2; ++j)
                    acc2[i][j] = fma2(ap[i], b2[j], acc2[i][j]);
        }
        __syncthreads();
    }

    // ---- epilogue ----
    #pragma unroll
    for (int i = 0; i < TM; ++i) {
        int gm = m0 + ty * TM + i;
        if (gm >= M) continue;
        float bv = bias ? bias[(size_t)gm * bias_stride] : 0.f;
        #pragma unroll
        for (int j = 0; j < TN2; ++j) {
            float vlo = __uint_as_float((unsigned)acc2[i][j]);
            float vhi = __uint_as_float((unsigned)(acc2[i][j] >> 32));
            int gn0 = n0 + tx * TN + 2 * j;
            if (gn0 < N) {
                float v = vlo + bv;
                if (Cadd) v += Cadd[(size_t)gn0 * ldc + gm];
                C[(size_t)gn0 * ldc + gm] = v;
            }
            if (gn0 + 1 < N) {
                float v = vhi + bv;
                if (Cadd) v += Cadd[(size_t)(gn0 + 1) * ldc + gm];
                C[(size_t)(gn0 + 1) * ldc + gm] = v;
            }
        }
    }
}

// ---------------- launch ----------------
extern "C" void kernel_launch(void* const* d_in, const int* in_sizes, int n_in,
                              void* d_out, int out_size)
{
    const float* inputs = (const float*)d_in[0];  // (1000,1,900)
    const float* state0 = (const float*)d_in[1];  // (1,4096)
    const float* W_ih   = (const float*)d_in[2];  // (4096,900)
    const float* W_hh   = (const float*)d_in[3];  // (4096,4096)
    const float* W_out  = (const float*)d_in[4];  // (900,4997)

    float* out    = (float*)d_out;                // outputs: SEQ*IDIM
    float* states = out + (size_t)SEQ * IDIM;     // states : SEQ*HDIM

    float *U = nullptr, *P = nullptr;
    cudaGetSymbolAddress((void**)&U, g_U);
    cudaGetSymbolAddress((void**)&P, g_P);

    cudaFuncSetAttribute(esn_loop_kernel,
                         cudaFuncAttributeMaxDynamicSharedMemorySize, (int)LOOP_SMEM);

    reset_kernel<<<1, 32>>>();

    // U[t][h] = W_ih[h,:] . inp[t,:]            M=4096 N=1000 K=900
    gemm_nt<128, 64><<<dim3(HDIM / 128, (SEQ + 63) / 64), 256>>>(
        W_ih, IDIM, inputs, IDIM, U, HDIM,
        nullptr, nullptr, 0, HDIM, SEQ, IDIM);

    // P[t][i] = W_out[i][0] + W_out[i,1:901] . inp[t,:]   M=900 N=1000 K=900
    gemm_nt<64, 64><<<dim3((IDIM + 63) / 64, (SEQ + 63) / 64), 256>>>(
        W_out + 1, WOLD, inputs, IDIM, P, IDIM,
        nullptr, W_out, WOLD, IDIM, SEQ, IDIM);

    // sequential recurrence: states[t] = tanh(U[t] + W_hh @ states[t-1])
    esn_loop_kernel<<<NBLK, TPB, LOOP_SMEM>>>(W_hh, state0, states);

    // out[t][i] = P[t][i] + W_out[i,901:] . states[t,:]   M=900 N=1000 K=4096
    gemm_nt<64, 64><<<dim3((IDIM + 63) / 64, (SEQ + 63) / 64), 256>>>(
        W_out + 1 + IDIM, WOLD, states, HDIM, out, IDIM,
        P, nullptr, 0, IDIM, SEQ, HDIM);
}

// round 13
// speedup vs baseline: 1.2184x; 1.0968x over previous
#include <cuda_runtime.h>
#include <cstdint>

#define SEQ   1000
#define IDIM  900
#define HDIM  4096
#define WOLD  (HDIM + IDIM + 1)   // 4997, W_out row stride
#define NBLK  148
#define TPB   512
#define CACHE_ROWS 13
// w cache + s buffer + reduction buffer (4*28 floats, padded)
#define LOOP_SMEM ((CACHE_ROWS * HDIM + HDIM + 128) * sizeof(float))

typedef unsigned long long ull;

// ---------------- scratch (static device globals; no allocation) ----------------
__device__ float g_U[SEQ * HDIM];   // W_ih @ inp[t]   (t-major)
__device__ float g_P[SEQ * IDIM];   // bias + input part of readout
__device__ int   g_bar;             // monotonic arrival counter

__device__ __forceinline__ int ld_acq(const int* p) {
    int v;
    asm volatile("ld.acquire.gpu.b32 %0, [%1];" : "=r"(v) : "l"(p) : "memory");
    return v;
}
__device__ __forceinline__ void arrive_release(int* p) {
    asm volatile("red.release.gpu.global.add.s32 [%0], 1;" :: "l"(p) : "memory");
}
// packed f32x2 FMA (Blackwell FFMA2 — only reachable via PTX)
__device__ __forceinline__ ull fma2(ull a, ull b, ull c) {
    ull d;
    asm("fma.rn.f32x2 %0, %1, %2, %3;" : "=l"(d) : "l"(a), "l"(b), "l"(c));
    return d;
}
__device__ __forceinline__ float accsum(ull a) {
    return __uint_as_float((unsigned)a) + __uint_as_float((unsigned)(a >> 32));
}
__device__ __forceinline__ ull dupf(float a) {
    ull d;
    unsigned ai = __float_as_uint(a);
    asm("mov.b64 %0, {%1, %1};" : "=l"(d) : "r"(ai));
    return d;
}

__global__ void reset_kernel() {
    if (threadIdx.x == 0) g_bar = 0;
}

// ---------------- persistent recurrence kernel (R10 structure — best) ----------
// s_{t} = tanh(U[t] + W_hh @ s_{t-1});  states[t] = s_t
__global__ __launch_bounds__(TPB, 1) void esn_loop_kernel(
    const float* __restrict__ W_hh,
    const float* __restrict__ s0,
    float* __restrict__ states)
{
    extern __shared__ float sh[];
    float* w_sh   = sh;                          // CACHE_ROWS * HDIM
    float* s_sh   = sh + CACHE_ROWS * HDIM;      // HDIM
    float* red_sh = s_sh + HDIM;                 // 4*28 floats

    const int bid  = blockIdx.x;
    const int tid  = threadIdx.x;
    const int warp = tid >> 5;
    const int lane = tid & 31;

    // 4096 = 148*27 + 100 -> blocks 0..99 get 28 rows, 100..147 get 27
    const int base  = bid * 27 + (bid < 100 ? bid : 100);
    const int nrows = (bid < 100) ? 28 : 27;

    // prologue: cache first CACHE_ROWS rows of this block's slice in SMEM
    {
        const float4* wsrc = (const float4*)(W_hh + (size_t)base * HDIM);
        float4* wdst = (float4*)w_sh;
        for (int i = tid; i < CACHE_ROWS * (HDIM / 4); i += TPB) wdst[i] = wsrc[i];
    }

    const int q  = warp >> 2;         // row-group 0..3
    const int kq = warp & 3;          // k-quarter
    const int kbase = kq * 256;       // in 16B units (256 ulonglong2 per quarter)

    const ulonglong2* wp0; const ulonglong2* wp1;
    const ulonglong2* wp2; const ulonglong2* wp3; const ulonglong2* wp6;
    {
        int r0 = q,      r1 = q + 4,  r2 = q + 8;
        int r3 = q + 12; int r6 = q + 24;
        int c3 = r3 < nrows ? r3 : nrows - 1;
        int c6 = r6 < nrows ? r6 : nrows - 1;   // row 27 invalid when nrows=27
        wp0 = (const ulonglong2*)(w_sh + r0 * HDIM);
        wp1 = (const ulonglong2*)(w_sh + r1 * HDIM);
        wp2 = (const ulonglong2*)(w_sh + r2 * HDIM);
        wp3 = (r3 < CACHE_ROWS) ? (const ulonglong2*)(w_sh + r3 * HDIM)
                                : (const ulonglong2*)(W_hh + (size_t)(base + c3) * HDIM);
        wp6 = (const ulonglong2*)(W_hh + (size_t)(base + c6) * HDIM);
    }
    // persistent register cache: k-quarter of rows q+16 (i=4) and q+20 (i=5)
    ulonglong2 wc4[8], wc5[8];
    {
        const ulonglong2* p4 = (const ulonglong2*)(W_hh + (size_t)(base + q + 16) * HDIM);
        const ulonglong2* p5 = (const ulonglong2*)(W_hh + (size_t)(base + q + 20) * HDIM);
        #pragma unroll
        for (int j = 0; j < 8; ++j) {
            wc4[j] = p4[kbase + lane + j * 32];
            wc5[j] = p5[kbase + lane + j * 32];
        }
    }

    const float* s_src = s0;

    for (int t = 0; t < SEQ; ++t) {
        float u = 0.f;
        if (warp == 0 && lane < 28) {
            int rc = lane < nrows ? lane : nrows - 1;
            u = g_U[(size_t)t * HDIM + base + rc];
        }

        // stage current state vector into SMEM (1024 float4, 512 threads)
        {
            const float4* src = (const float4*)s_src;
            float4* dst = (float4*)s_sh;
            float4 v0 = src[tid];
            float4 v1 = src[tid + TPB];
            dst[tid] = v0;
            dst[tid + TPB] = v1;
        }
        __syncthreads();

        {
            const ulonglong2* sq = (const ulonglong2*)s_sh;
            ull a0 = 0, a1 = 0, a2 = 0, a3 = 0, a4 = 0, a5 = 0, a6 = 0;

            #pragma unroll
            for (int j = 0; j < 8; ++j) {
                const int idx = kbase + lane + j * 32;
                ulonglong2 s2 = sq[idx];
                ulonglong2 w0 = wp0[idx];
                ulonglong2 w1 = wp1[idx];
                ulonglong2 w2 = wp2[idx];
                ulonglong2 w3 = wp3[idx];
                ulonglong2 w6 = wp6[idx];
                a0 = fma2(w0.x, s2.x, a0); a0 = fma2(w0.y, s2.y, a0);
                a1 = fma2(w1.x, s2.x, a1); a1 = fma2(w1.y, s2.y, a1);
                a2 = fma2(w2.x, s2.x, a2); a2 = fma2(w2.y, s2.y, a2);
                a3 = fma2(w3.x, s2.x, a3); a3 = fma2(w3.y, s2.y, a3);
                a4 = fma2(wc4[j].x, s2.x, a4); a4 = fma2(wc4[j].y, s2.y, a4);
                a5 = fma2(wc5[j].x, s2.x, a5); a5 = fma2(wc5[j].y, s2.y, a5);
                a6 = fma2(w6.x, s2.x, a6); a6 = fma2(w6.y, s2.y, a6);
            }

            float r0 = accsum(a0), r1 = accsum(a1), r2 = accsum(a2), r3 = accsum(a3);
            float r4 = accsum(a4), r5 = accsum(a5), r6 = accsum(a6);
            #pragma unroll
            for (int off = 16; off; off >>= 1) {
                r0 += __shfl_xor_sync(0xffffffffu, r0, off);
                r1 += __shfl_xor_sync(0xffffffffu, r1, off);
                r2 += __shfl_xor_sync(0xffffffffu, r2, off);
                r3 += __shfl_xor_sync(0xffffffffu, r3, off);
                r4 += __shfl_xor_sync(0xffffffffu, r4, off);
                r5 += __shfl_xor_sync(0xffffffffu, r5, off);
                r6 += __shfl_xor_sync(0xffffffffu, r6, off);
            }
            if (lane == 0) {
                float* rp = red_sh + kq * 28 + q;
                rp[0]  = r0; rp[4]  = r1; rp[8]  = r2; rp[12] = r3;
                rp[16] = r4; rp[20] = r5; rp[24] = r6;
            }
        }
        __syncthreads();   // partials visible

        if (warp == 0 && lane < 28) {
            float v = red_sh[lane] + red_sh[28 + lane]
                    + red_sh[56 + lane] + red_sh[84 + lane];
            if (lane < nrows)
                states[(size_t)t * HDIM + base + lane] = tanhf(v + u);
        }
        __syncthreads();   // states STGs of this step issued

        if (t < SEQ - 1) {
            if (tid == 0) arrive_release(&g_bar);   // release: orders the STGs
            if (warp == 15) {                       // poller
                const int target = (t + 1) * NBLK;
                while (ld_acq(&g_bar) < target) { }
            }
            __syncthreads();   // barrier passed; also protects s_sh reuse
        }

        s_src = states + (size_t)t * HDIM;
    }
}

// ---------------- fp32 GEMM, DOUBLE-BUFFERED:
// C[n][m] = (bias[m]) + (Cadd[n][m]) + sum_k A[m][k]*B[n][k]
// 256 threads, BMxBN tile, BK=8, one __syncthreads per K-iteration;
// next tile's LDG issues before the current tile's compute (latency hidden).
template<int BM, int BN>
__global__ __launch_bounds__(256, 2) void gemm_nt(
    const float* __restrict__ A, int lda,
    const float* __restrict__ B, int ldb,
    float* __restrict__ C, int ldc,
    const float* __restrict__ Cadd,
    const float* __restrict__ bias, int bias_stride,
    int M, int N, int K)
{
    constexpr int BK = 8;
    constexpr int TM = BM / 16;
    constexpr int TN = BN / 16;
    constexpr int TN2 = TN / 2;
    constexpr int ASEG = (BM * 2 + 255) / 256;   // float4 segments per thread (A)
    constexpr int BSEG = (BN * 2 + 255) / 256;
    __shared__ float As[2][BK][BM + 4];
    __shared__ float Bs[2][BK][BN + 4];

    const int tid = threadIdx.x;
    const int tx = tid & 15;
    const int ty = tid >> 4;
    const int m0 = blockIdx.x * BM;
    const int n0 = blockIdx.y * BN;

    const bool a_vec = ((reinterpret_cast<uintptr_t>(A) & 15) == 0) && ((lda & 3) == 0);
    const bool b_vec = ((reinterpret_cast<uintptr_t>(B) & 15) == 0) && ((ldb & 3) == 0);

    float4 ra[ASEG], rb[BSEG];

    // fetch tile at kt into registers
    auto fetch = [&](int kt) {
        #pragma unroll
        for (int s = 0; s < ASEG; ++s) {
            int i = s * 256 + tid;
            float v0 = 0.f, v1 = 0.f, v2 = 0.f, v3 = 0.f;
            if (i < BM * 2) {
                int m = i >> 1;
                int kq = (i & 1) * 4;
                int gm = m0 + m;
                int gk = kt + kq;
                if (gm < M) {
                    const float* p = A + (size_t)gm * lda + gk;
                    int rem = K - gk;
                    if (a_vec && rem >= 4) {
                        float4 v = *(const float4*)p;
                        v0 = v.x; v1 = v.y; v2 = v.z; v3 = v.w;
                    } else {
                        if (rem > 0) v0 = p[0];
                        if (rem > 1) v1 = p[1];
                        if (rem > 2) v2 = p[2];
                        if (rem > 3) v3 = p[3];
                    }
                }
            }
            ra[s] = make_float4(v0, v1, v2, v3);
        }
        #pragma unroll
        for (int s = 0; s < BSEG; ++s) {
            int i = s * 256 + tid;
            float v0 = 0.f, v1 = 0.f, v2 = 0.f, v3 = 0.f;
            if (i < BN * 2) {
                int n = i >> 1;
                int kq = (i & 1) * 4;
                int gn = n0 + n;
                int gk = kt + kq;
                if (gn < N) {
                    const float* p = B + (size_t)gn * ldb + gk;
                    int rem = K - gk;
                    if (b_vec && rem >= 4) {
                        float4 v = *(const float4*)p;
                        v0 = v.x; v1 = v.y; v2 = v.z; v3 = v.w;
                    } else {
                        if (rem > 0) v0 = p[0];
                        if (rem > 1) v1 = p[1];
                        if (rem > 2) v2 = p[2];
                        if (rem > 3) v3 = p[3];
                    }
                }
            }
            rb[s] = make_float4(v0, v1, v2, v3);
        }
    };
    // store register tile into buffer buf (transposed)
    auto store = [&](int buf) {
        #pragma unroll
        for (int s = 0; s < ASEG; ++s) {
            int i = s * 256 + tid;
            if (i < BM * 2) {
                int m = i >> 1;
                int kq = (i & 1) * 4;
                As[buf][kq + 0][m] = ra[s].x; As[buf][kq + 1][m] = ra[s].y;
                As[buf][kq + 2][m] = ra[s].z; As[buf][kq + 3][m] = ra[s].w;
            }
        }
        #pragma unroll
        for (int s = 0; s < BSEG; ++s) {
            int i = s * 256 + tid;
            if (i < BN * 2) {
                int n = i >> 1;
                int kq = (i & 1) * 4;
                Bs[buf][kq + 0][n] = rb[s].x; Bs[buf][kq + 1][n] = rb[s].y;
                Bs[buf][kq + 2][n] = rb[s].z; Bs[buf][kq + 3][n] = rb[s].w;
            }
        }
    };

    ull acc2[TM][TN2];
    #pragma unroll
    for (int i = 0; i < TM; ++i)
        #pragma unroll
        for (int j = 0; j < TN2; ++j) acc2[i][j] = 0ull;

    fetch(0);
    store(0);
    __syncthreads();

    int buf = 0;
    for (int kt = BK; kt < K; kt += BK) {
        fetch(kt);                       // LDGs issue early, hide under compute

        #pragma unroll
        for (int kk = 0; kk < BK; ++kk) {
            ull ap[TM], b2[TN2];
            #pragma unroll
            for (int i = 0; i < TM; ++i) ap[i] = dupf(As[buf][kk][ty * TM + i]);
            #pragma unroll
            for (int j = 0; j < TN2; ++j)
                b2[j] = *(const ull*)&Bs[buf][kk][tx * TN + 2 * j];
            #pragma unroll
            for (int i = 0; i < TM; ++i)
                #pragma unroll
                for (int j = 0; j < TN2; ++j)
                    acc2[i][j] = fma2(ap[i], b2[j], acc2[i][j]);
        }

        store(buf ^ 1);
        __syncthreads();                 // ONE sync per iteration
        buf ^= 1;
    }
    // last tile
    #pragma unroll
    for (int kk = 0; kk < BK; ++kk) {
        ull ap[TM], b2[TN2];
        #pragma unroll
        for (int i = 0; i < TM; ++i) ap[i] = dupf(As[buf][kk][ty * TM + i]);
        #pragma unroll
        for (int j = 0; j < TN2; ++j)
            b2[j] = *(const ull*)&Bs[buf][kk][tx * TN + 2 * j];
        #pragma unroll
        for (int i = 0; i < TM; ++i)
            #pragma unroll
            for (int j = 0; j < TN2; ++j)
                acc2[i][j] = fma2(ap[i], b2[j], acc2[i][j]);
    }

    // ---- epilogue ----
    #pragma unroll
    for (int i = 0; i < TM; ++i) {
        int gm = m0 + ty * TM + i;
        if (gm >= M) continue;
        float bv = bias ? bias[(size_t)gm * bias_stride] : 0.f;
        #pragma unroll
        for (int j = 0; j < TN2; ++j) {
            float vlo = __uint_as_float((unsigned)acc2[i][j]);
            float vhi = __uint_as_float((unsigned)(acc2[i][j] >> 32));
            int gn0 = n0 + tx * TN + 2 * j;
            if (gn0 < N) {
                float v = vlo + bv;
                if (Cadd) v += Cadd[(size_t)gn0 * ldc + gm];
                C[(size_t)gn0 * ldc + gm] = v;
            }
            if (gn0 + 1 < N) {
                float v = vhi + bv;
                if (Cadd) v += Cadd[(size_t)(gn0 + 1) * ldc + gm];
                C[(size_t)(gn0 + 1) * ldc + gm] = v;
            }
        }
    }
}

// ---------------- launch ----------------
extern "C" void kernel_launch(void* const* d_in, const int* in_sizes, int n_in,
                              void* d_out, int out_size)
{
    const float* inputs = (const float*)d_in[0];  // (1000,1,900)
    const float* state0 = (const float*)d_in[1];  // (1,4096)
    const float* W_ih   = (const float*)d_in[2];  // (4096,900)
    const float* W_hh   = (const float*)d_in[3];  // (4096,4096)
    const float* W_out  = (const float*)d_in[4];  // (900,4997)

    float* out    = (float*)d_out;                // outputs: SEQ*IDIM
    float* states = out + (size_t)SEQ * IDIM;     // states : SEQ*HDIM

    float *U = nullptr, *P = nullptr;
    cudaGetSymbolAddress((void**)&U, g_U);
    cudaGetSymbolAddress((void**)&P, g_P);

    cudaFuncSetAttribute(esn_loop_kernel,
                         cudaFuncAttributeMaxDynamicSharedMemorySize, (int)LOOP_SMEM);

    reset_kernel<<<1, 32>>>();

    // U[t][h] = W_ih[h,:] . inp[t,:]            M=4096 N=1000 K=900
    gemm_nt<128, 64><<<dim3(HDIM / 128, (SEQ + 63) / 64), 256>>>(
        W_ih, IDIM, inputs, IDIM, U, HDIM,
        nullptr, nullptr, 0, HDIM, SEQ, IDIM);

    // P[t][i] = W_out[i][0] + W_out[i,1:901] . inp[t,:]   M=900 N=1000 K=900
    gemm_nt<64, 64><<<dim3((IDIM + 63) / 64, (SEQ + 63) / 64), 256>>>(
        W_out + 1, WOLD, inputs, IDIM, P, IDIM,
        nullptr, W_out, WOLD, IDIM, SEQ, IDIM);

    // sequential recurrence: states[t] = tanh(U[t] + W_hh @ states[t-1])
    esn_loop_kernel<<<NBLK, TPB, LOOP_SMEM>>>(W_hh, state0, states);

    // out[t][i] = P[t][i] + W_out[i,901:] . states[t,:]   M=900 N=1000 K=4096
    gemm_nt<64, 64><<<dim3((IDIM + 63) / 64, (SEQ + 63) / 64), 256>>>(
        W_out + 1 + IDIM, WOLD, states, HDIM, out, IDIM,
        P, nullptr, 0, IDIM, SEQ, HDIM);
}